// round 2
// baseline (speedup 1.0000x reference)
#include <cuda_runtime.h>
#include <cuda_bf16.h>
#include <cstdint>

#define LROW 2048
#define HID  128
#define KS   9
#define PAD  4
#define TPB  256
#define OPT  8   // outputs per thread: 256*8 = 2048 = one full row per CTA

typedef unsigned long long u64;

#define PACK_F32X2(out, lo, hi) \
    asm("mov.b64 %0, {%1, %2};" : "=l"(out) : "f"(lo), "f"(hi))
#define UNPACK_F32X2(lo, hi, in) \
    asm("mov.b64 {%0, %1}, %2;" : "=f"(lo), "=f"(hi) : "l"(in))
#define FMA_F32X2(d, a, b, c) \
    asm("fma.rn.f32x2 %0, %1, %2, %3;" : "=l"(d) : "l"(a), "l"(b), "l"(c))

__global__ __launch_bounds__(TPB)
void simconv1d_kernel(const float* __restrict__ x,
                      const float* __restrict__ W1,
                      const float* __restrict__ b1,
                      const float* __restrict__ W2,
                      const float* __restrict__ b2,
                      float* __restrict__ out)
{
    __shared__ __align__(16) float xs[LROW + 2 * PAD];
    __shared__ __align__(16) float W1s[KS * HID];
    __shared__ __align__(16) float b1s[HID];
    __shared__ __align__(16) float W2s[HID];

    const int row = blockIdx.x;          // b*64 + h
    const int tid = threadIdx.x;
    const float* xr = x + (size_t)row * LROW;

    // Stage x row into shared (vectorized), zero the halos.
    {
        const float4* x4  = (const float4*)xr;
        float4*       xs4 = (float4*)(xs + PAD);   // +4 floats = 16B, aligned
        #pragma unroll
        for (int i = tid; i < LROW / 4; i += TPB) xs4[i] = x4[i];
        if (tid < PAD) { xs[tid] = 0.0f; xs[LROW + PAD + tid] = 0.0f; }
    }
    // Stage weights.
    for (int i = tid; i < KS * HID; i += TPB) W1s[i] = W1[i];
    if (tid < HID) { W2s[tid] = W2[tid]; b1s[tid] = b1[tid]; }
    __syncthreads();

    // Sliding window: outputs [o0, o0+8), taps need x[o0-4 .. o0+11] = xs[o0 .. o0+15]
    const int o0 = tid * OPT;
    float xv[OPT + KS - 1];
    #pragma unroll
    for (int i = 0; i < OPT + KS - 1; i++) xv[i] = xs[o0 + i];

    // Duplicate x taps into packed (x, x) pairs ONCE — reused for all 64 d-pairs.
    u64 xdup[OPT + KS - 1];
    #pragma unroll
    for (int i = 0; i < OPT + KS - 1; i++) PACK_F32X2(xdup[i], xv[i], xv[i]);

    float y[OPT];
    #pragma unroll
    for (int j = 0; j < OPT; j++) y[j] = 0.0f;

    const float bias2 = b2[0];

    // Process hidden units in packed pairs (d, d+1).
    #pragma unroll 1
    for (int d = 0; d < HID; d += 2) {
        // Packed weights: (W1[k][d], W1[k][d+1]) are adjacent & 8B-aligned (d even).
        u64 wp[KS];
        #pragma unroll
        for (int k = 0; k < KS; k++)
            wp[k] = *(const u64*)&W1s[k * HID + d];   // warp-uniform broadcast lds64

        const u64 bb2 = *(const u64*)&b1s[d];
        u64 hp[OPT];
        #pragma unroll
        for (int j = 0; j < OPT; j++) hp[j] = bb2;

        #pragma unroll
        for (int k = 0; k < KS; k++) {
            #pragma unroll
            for (int j = 0; j < OPT; j++)
                FMA_F32X2(hp[j], xdup[j + k], wp[k], hp[j]);  // 2 FMA / instr
        }

        const float w2a = W2s[d];
        const float w2b = W2s[d + 1];
        #pragma unroll
        for (int j = 0; j < OPT; j++) {
            float lo, hi;
            UNPACK_F32X2(lo, hi, hp[j]);
            y[j] = fmaf(fmaxf(lo, 0.0f), w2a, y[j]);
            y[j] = fmaf(fmaxf(hi, 0.0f), w2b, y[j]);
        }
    }

    float* orow = out + (size_t)row * LROW + o0;
    #pragma unroll
    for (int j = 0; j < OPT; j++) orow[j] = y[j] + bias2;
}

extern "C" void kernel_launch(void* const* d_in, const int* in_sizes, int n_in,
                              void* d_out, int out_size)
{
    const float* x  = (const float*)d_in[0];  // (8, 64, 2048)
    const float* W1 = (const float*)d_in[1];  // (9, 128)
    const float* b1 = (const float*)d_in[2];  // (128,)
    const float* W2 = (const float*)d_in[3];  // (128, 1)
    const float* b2 = (const float*)d_in[4];  // (1,)
    float* out = (float*)d_out;               // (8, 64, 2048)

    const int rows = 8 * 64;
    simconv1d_kernel<<<rows, TPB>>>(x, W1, b1, W2, b2, out);
}